// round 13
// baseline (speedup 1.0000x reference)
#include <cuda_runtime.h>
#include <cstdint>

// Problem constants (fixed by reference setup_inputs):
//   X: (16, 2, 262144) fp32 ; WINDOW=1024, HOP=256
//   n_frames = (262144-1024)/256 + 1 = 1021
//   out: (16, 2, 1024, 1021) fp32, out[bc][w][f] = X[bc][f*256 + w]
// Decompose w = q*256 + r  ->  out[bc][q*256+r][f] = S[f+q][r],
// where S = X[bc] viewed as (1024, 256).  => 4 shifted transposes.

#define HOPK   256
#define NF     1021          // frames
#define NJ     1024          // rows of S = T/HOP
#define NW     1024          // window
#define TF     128           // frames per tile
#define TFP    (TF + 3)      // +3 rows for q in [0,4); 131 (odd -> conflict-free)
#define TR     32            // r values per tile

__global__ __launch_bounds__(256)
void splitsignal_kernel(const float* __restrict__ in, float* __restrict__ out) {
    // smem[r_local][j_local], row stride 131 (odd) -> bank-conflict-free both phases
    __shared__ float s[TR][TFP];

    const int f0 = blockIdx.x * TF;     // frame tile origin
    const int r0 = blockIdx.y * TR;     // r tile origin
    const int bc = blockIdx.z;          // fused (b, c) channel, 0..31
    const int tx = threadIdx.x;         // 0..31
    const int ty = threadIdx.y;         // 0..7
    const int tid = ty * 32 + tx;

    // ---------------- Load phase: S rows [f0, f0+131) x cols [r0, r0+32) ----------------
    // 131 rows * 8 float4/row = 1048 float4 loads, 256 threads -> <=5 iterations.
    const float* base_in = in + (size_t)bc * (NJ * HOPK) + r0;

    #pragma unroll
    for (int it = 0; it < 5; it++) {
        int idx = tid + it * 256;
        if (idx < TFP * (TR / 4)) {
            int jj = idx >> 3;          // row within tile
            int c4 = idx & 7;           // float4 column
            int j  = f0 + jj;           // row of S
            if (j < NJ) {
                float4 v = *reinterpret_cast<const float4*>(
                    base_in + (size_t)j * HOPK + c4 * 4);
                // STS banks: ((c4*4+i)*131 + jj) mod 32 = (c4*12 + 3i + jj) mod 32
                // -> all 32 lanes hit distinct banks (verified).
                s[c4 * 4 + 0][jj] = v.x;
                s[c4 * 4 + 1][jj] = v.y;
                s[c4 * 4 + 2][jj] = v.z;
                s[c4 * 4 + 3][jj] = v.w;
            }
        }
    }
    __syncthreads();

    // ---------------- Store phase: out[bc][q*256 + r0+rr][f0+fl] = s[rr][fl+q] ----------
    // fl = tx + 32k  -> LDS bank = tx (conflict-free), STG coalesced along f.
    float* base_out = out + (size_t)bc * ((size_t)NW * NF);

    #pragma unroll
    for (int q = 0; q < 4; q++) {
        #pragma unroll
        for (int m = 0; m < 4; m++) {
            const int rr = ty + m * 8;
            float* orow = base_out + (size_t)(q * HOPK + r0 + rr) * NF + f0;
            #pragma unroll
            for (int k = 0; k < 4; k++) {
                const int fl = tx + k * 32;
                if (f0 + fl < NF) {
                    orow[fl] = s[rr][fl + q];
                }
            }
        }
    }
}

extern "C" void kernel_launch(void* const* d_in, const int* in_sizes, int n_in,
                              void* d_out, int out_size) {
    (void)in_sizes; (void)n_in; (void)out_size;
    const float* X = (const float*)d_in[0];
    float* out = (float*)d_out;

    // grid: 8 f-tiles (8*128=1024 >= 1021), 8 r-tiles (256/32), 32 channels (16*2)
    dim3 grid((NF + TF - 1) / TF, HOPK / TR, 32);
    dim3 block(32, 8);
    splitsignal_kernel<<<grid, block>>>(X, out);
}

// round 14
// speedup vs baseline: 1.0260x; 1.0260x over previous
#include <cuda_runtime.h>
#include <cstdint>

// Problem constants (fixed by reference setup_inputs):
//   X: (16, 2, 262144) fp32 ; WINDOW=1024, HOP=256
//   n_frames = (262144-1024)/256 + 1 = 1021
//   out: (16, 2, 1024, 1021) fp32, out[bc][w][f] = X[bc][f*256 + w]
// Decompose w = q*256 + r  ->  out[bc][q*256+r][f] = S[f+q][r],
// where S = X[bc] viewed as (1024, 256).  => 4 shifted transposes.

#define HOPK   256
#define NF     1021          // frames
#define NJ     1024          // rows of S = T/HOP
#define NW     1024          // window
#define TF     128           // frames per tile
#define TFP    (TF + 3)      // +3 rows for q in [0,4); 131 (odd -> conflict-free)
#define TR     32            // r values per tile

__global__ __launch_bounds__(256)
void splitsignal_kernel(const float* __restrict__ in, float* __restrict__ out) {
    // smem[r_local][j_local], row stride 131 (odd) -> bank-conflict-free both phases
    __shared__ float s[TR][TFP];

    const int f0 = blockIdx.x * TF;     // frame tile origin
    const int r0 = blockIdx.y * TR;     // r tile origin
    const int bc = blockIdx.z;          // fused (b, c) channel, 0..31
    const int tx = threadIdx.x;         // 0..31
    const int ty = threadIdx.y;         // 0..7
    const int tid = ty * 32 + tx;

    // ---------------- Load phase: S rows [f0, f0+131) x cols [r0, r0+32) ----------------
    // 131 rows * 8 float4/row = 1048 float4 loads, 256 threads -> <=5 iterations.
    const float* base_in = in + (size_t)bc * (NJ * HOPK) + r0;

    #pragma unroll
    for (int it = 0; it < 5; it++) {
        int idx = tid + it * 256;
        if (idx < TFP * (TR / 4)) {
            int jj = idx >> 3;          // row within tile
            int c4 = idx & 7;           // float4 column
            int j  = f0 + jj;           // row of S
            if (j < NJ) {
                float4 v = *reinterpret_cast<const float4*>(
                    base_in + (size_t)j * HOPK + c4 * 4);
                // STS banks: ((c4*4+i)*131 + jj) mod 32 = (c4*12 + 3i + jj) mod 32
                // -> all 32 lanes hit distinct banks (verified).
                s[c4 * 4 + 0][jj] = v.x;
                s[c4 * 4 + 1][jj] = v.y;
                s[c4 * 4 + 2][jj] = v.z;
                s[c4 * 4 + 3][jj] = v.w;
            }
        }
    }
    __syncthreads();

    // ---------------- Store phase: out[bc][q*256 + r0+rr][f0+fl] = s[rr][fl+q] ----------
    // fl = tx + 32k  -> LDS bank = tx (conflict-free), STG coalesced along f.
    float* base_out = out + (size_t)bc * ((size_t)NW * NF);

    #pragma unroll
    for (int q = 0; q < 4; q++) {
        #pragma unroll
        for (int m = 0; m < 4; m++) {
            const int rr = ty + m * 8;
            float* orow = base_out + (size_t)(q * HOPK + r0 + rr) * NF + f0;
            #pragma unroll
            for (int k = 0; k < 4; k++) {
                const int fl = tx + k * 32;
                if (f0 + fl < NF) {
                    orow[fl] = s[rr][fl + q];
                }
            }
        }
    }
}

extern "C" void kernel_launch(void* const* d_in, const int* in_sizes, int n_in,
                              void* d_out, int out_size) {
    (void)in_sizes; (void)n_in; (void)out_size;
    const float* X = (const float*)d_in[0];
    float* out = (float*)d_out;

    // grid: 8 f-tiles (8*128=1024 >= 1021), 8 r-tiles (256/32), 32 channels (16*2)
    dim3 grid((NF + TF - 1) / TF, HOPK / TR, 32);
    dim3 block(32, 8);
    splitsignal_kernel<<<grid, block>>>(X, out);
}